// round 12
// baseline (speedup 1.0000x reference)
#include <cuda_runtime.h>
#include <cuda_bf16.h>
#include <cuda_fp16.h>

// Problem constants (shapes fixed by the dataset)
#define NN   8192
#define EE   65536
#define INC  64
#define OUTC 16
#define EF   8
#define L1   48
#define L2   32

#define C1TOT 480   // Y1 (EF*L1=384) + Z1 (48) + R1 (48), K=64
#define C2TOT 320   // Y2 (EF*L2=256) + Z2 (32) + R2 (32), K=48

#define NPB  16  // nodes per block, node1
#define NPB2 32  // nodes per block, node2

// ---------------- scratch (device globals; no allocation allowed) ----------
__device__ __half dY1h[(size_t)NN * EF * L1];  // fp16 gather payload  6.3 MB
__device__ float  dZ1[NN * L1];
__device__ float  dAgg1[NN * L1];
__device__ __half dY2h[(size_t)NN * EF * L2];  // fp16 gather payload  4.2 MB
__device__ float  dZ2[NN * L2];
__device__ float  dAgg2[NN * L2];
__device__ float  dDeg[NN];
__device__ float  dRs[NN];                     // rsqrt(deg)
__device__ float  dG[NN * 2 * OUTC];           // [n][c], c<16 mu, c>=16 ls
__device__ float  dW1km[64 * C1TOT];           // k-major: [k][c]
__device__ float  dW2km[48 * C2TOT];           // k-major: [k][c]
__device__ float  dWgT[32 * 32];               // [c][k]

__device__ __forceinline__ void red_add_v4(float* addr, float4 v) {
    asm volatile("red.global.add.v4.f32 [%0], {%1, %2, %3, %4};"
                 :: "l"(addr), "f"(v.x), "f"(v.y), "f"(v.z), "f"(v.w) : "memory");
}
__device__ __forceinline__ void fma2(unsigned long long& acc, unsigned long long a,
                                     unsigned long long b) {
    asm("fma.rn.f32x2 %0, %1, %2, %0;" : "+l"(acc) : "l"(a), "l"(b));
}
__device__ __forceinline__ unsigned long long pack2(float w) {
    unsigned long long r;
    asm("mov.b64 %0, {%1, %1};" : "=l"(r) : "f"(w));
    return r;
}
__device__ __forceinline__ void unpack2(unsigned long long v, float& lo, float& hi) {
    asm("mov.b64 {%0, %1}, %2;" : "=f"(lo), "=f"(hi) : "l"(v));
}

// ---------------- kernel 0: weight pre-transpose (k-major) ------------------
__global__ void prep_weights(const float* __restrict__ nn1_w, const float* __restrict__ nn1_b,
                             const float* __restrict__ root1,
                             const float* __restrict__ nn2_w, const float* __restrict__ nn2_b,
                             const float* __restrict__ root2,
                             const float* __restrict__ mu_w,  const float* __restrict__ ls_w) {
    int idx = blockIdx.x * blockDim.x + threadIdx.x;
    if (idx < C1TOT * 64) {
        int k = idx / C1TOT, c = idx - k * C1TOT;
        float v;
        if (c < EF * L1)            { int f = c / L1, j = c % L1; v = nn1_w[f * (INC * L1) + k * L1 + j]; }
        else if (c < EF * L1 + L1)  { int j = c - EF * L1;        v = nn1_b[k * L1 + j]; }
        else                        { int j = c - EF * L1 - L1;   v = root1[k * L1 + j]; }
        dW1km[idx] = v;
    }
    int i2 = idx - C1TOT * 64;
    if (i2 >= 0 && i2 < C2TOT * 48) {
        int k = i2 / C2TOT, c = i2 - k * C2TOT;
        float v;
        if (c < EF * L2)            { int f = c / L2, j = c % L2; v = nn2_w[f * (L1 * L2) + k * L2 + j]; }
        else if (c < EF * L2 + L2)  { int j = c - EF * L2;        v = nn2_b[k * L2 + j]; }
        else                        { int j = c - EF * L2 - L2;   v = root2[k * L2 + j]; }
        dW2km[i2] = v;
    }
    int i3 = i2 - C2TOT * 48;
    if (i3 >= 0 && i3 < 32 * 32) {
        int c = i3 >> 5, k = i3 & 31;
        dWgT[i3] = (c < OUTC) ? mu_w[k * OUTC + c] : ls_w[k * OUTC + (c - OUTC)];
    }
}

// ---------------- kernel: node transform layer 1 (f32x2 packed) -------------
__global__ __launch_bounds__(C1TOT) void node1_kernel(const float* __restrict__ x,
                                                      const float* __restrict__ bias1) {
    __shared__ float xs[64 * NPB];
    int n0 = blockIdx.x * NPB;
    int c = threadIdx.x;
    if (c < 256) {                       // 16 nodes x 16 k-groups of 4
        int n = c & 15, k0 = (c >> 4) * 4;
        float4 v = *(const float4*)(x + (size_t)(n0 + n) * 64 + k0);
        xs[(k0 + 0) * NPB + n] = v.x;
        xs[(k0 + 1) * NPB + n] = v.y;
        xs[(k0 + 2) * NPB + n] = v.z;
        xs[(k0 + 3) * NPB + n] = v.w;
    }
    if (c < NPB) dDeg[n0 + c] = 1.0f;
    __syncthreads();

    unsigned long long acc2[NPB / 2];
#pragma unroll
    for (int p = 0; p < NPB / 2; p++) acc2[p] = 0ull;
    const float* wp = dW1km + c;
#pragma unroll 4
    for (int k = 0; k < 64; k++) {
        unsigned long long w2 = pack2(wp[k * C1TOT]);
        const ulonglong2* xp = (const ulonglong2*)(xs + k * NPB);
#pragma unroll
        for (int i = 0; i < NPB / 4; i++) {
            ulonglong2 xv = xp[i];
            fma2(acc2[2 * i + 0], xv.x, w2);
            fma2(acc2[2 * i + 1], xv.y, w2);
        }
    }
    float acc[NPB];
#pragma unroll
    for (int p = 0; p < NPB / 2; p++) unpack2(acc2[p], acc[2 * p], acc[2 * p + 1]);

    if (c < EF * L1) {
#pragma unroll
        for (int n = 0; n < NPB; n++)
            dY1h[(size_t)(n0 + n) * (EF * L1) + c] = __float2half(acc[n]);
    } else if (c < EF * L1 + L1) {
        int j = c - EF * L1;
#pragma unroll
        for (int n = 0; n < NPB; n++) dZ1[(n0 + n) * L1 + j] = acc[n];
    } else {
        int j = c - EF * L1 - L1;
        float b = bias1[j];
#pragma unroll
        for (int n = 0; n < NPB; n++) dAgg1[(n0 + n) * L1 + j] = acc[n] + b;
    }
}

// ---------------- kernel: edge scatter layer 1 (8 cols/thread) --------------
// thread = (edge, q), q in [0,6): 8 consecutive j columns
__global__ void edge1_kernel(const int* __restrict__ ei, const float* __restrict__ ea) {
    int idx = blockIdx.x * blockDim.x + threadIdx.x;
    if (idx >= EE * 6) return;
    int e = idx / 6;
    int q = idx - e * 6;
    int j = q * 8;
    int s = ei[e];
    int d = ei[EE + e];
    float4 ea0 = ((const float4*)(ea + e * EF))[0];
    float4 ea1 = ((const float4*)(ea + e * EF))[1];
    const __half* y = dY1h + (size_t)s * (EF * L1) + j;
    float4 m0 = *(const float4*)(dZ1 + s * L1 + j);
    float4 m1 = *(const float4*)(dZ1 + s * L1 + j + 4);
#define E1STEP(F, A) { \
    uint4 r = *(const uint4*)(y + (F) * L1); \
    float2 f0 = __half22float2(*reinterpret_cast<const __half2*>(&r.x)); \
    float2 f1 = __half22float2(*reinterpret_cast<const __half2*>(&r.y)); \
    float2 f2 = __half22float2(*reinterpret_cast<const __half2*>(&r.z)); \
    float2 f3 = __half22float2(*reinterpret_cast<const __half2*>(&r.w)); \
    m0.x += (A) * f0.x; m0.y += (A) * f0.y; m0.z += (A) * f1.x; m0.w += (A) * f1.y; \
    m1.x += (A) * f2.x; m1.y += (A) * f2.y; m1.z += (A) * f3.x; m1.w += (A) * f3.y; }
    E1STEP(0, ea0.x) E1STEP(1, ea0.y) E1STEP(2, ea0.z) E1STEP(3, ea0.w)
    E1STEP(4, ea1.x) E1STEP(5, ea1.y) E1STEP(6, ea1.z) E1STEP(7, ea1.w)
#undef E1STEP
    if (q == 0) atomicAdd(&dDeg[d], 1.0f);
    red_add_v4(&dAgg1[d * L1 + j], m0);
    red_add_v4(&dAgg1[d * L1 + j + 4], m1);
}

// ---------------- kernel: node transform layer 2 (scalar, NPB2=32) ----------
__global__ __launch_bounds__(C2TOT) void node2_kernel(const float* __restrict__ bias2) {
    __shared__ float hs[NPB2 * 48];
    int n0 = blockIdx.x * NPB2;
    int c = threadIdx.x;
    for (int i = c; i < NPB2 * 48 / 4; i += C2TOT) {
        float4 v = ((const float4*)(dAgg1 + n0 * L1))[i];
        v.x = fmaxf(v.x, 0.f); v.y = fmaxf(v.y, 0.f);
        v.z = fmaxf(v.z, 0.f); v.w = fmaxf(v.w, 0.f);
        ((float4*)hs)[i] = v;
    }
    if (c < NPB2) dRs[n0 + c] = rsqrtf(dDeg[n0 + c]);  // deg final after edge1
    __syncthreads();

    float acc[NPB2];
#pragma unroll
    for (int n = 0; n < NPB2; n++) acc[n] = 0.0f;
    const float* wp = dW2km + c;
#pragma unroll 2
    for (int k4 = 0; k4 < 12; k4++) {
        float w0 = wp[(4 * k4 + 0) * C2TOT];
        float w1 = wp[(4 * k4 + 1) * C2TOT];
        float w2 = wp[(4 * k4 + 2) * C2TOT];
        float w3 = wp[(4 * k4 + 3) * C2TOT];
#pragma unroll
        for (int n = 0; n < NPB2; n++) {
            float4 xv = ((const float4*)(hs + n * 48))[k4];  // broadcast LDS
            acc[n] += xv.x * w0 + xv.y * w1 + xv.z * w2 + xv.w * w3;
        }
    }
    if (c < EF * L2) {
#pragma unroll
        for (int n = 0; n < NPB2; n++)
            dY2h[(size_t)(n0 + n) * (EF * L2) + c] = __float2half(acc[n]);
    } else if (c < EF * L2 + L2) {
        int j = c - EF * L2;
#pragma unroll
        for (int n = 0; n < NPB2; n++) dZ2[(n0 + n) * L2 + j] = acc[n];
    } else {
        int j = c - EF * L2 - L2;
        float b = bias2[j];
#pragma unroll
        for (int n = 0; n < NPB2; n++) dAgg2[(n0 + n) * L2 + j] = acc[n] + b;
    }
}

// ---------------- kernel: edge scatter layer 2 (8 cols/thread) --------------
__global__ void edge2_kernel(const int* __restrict__ ei, const float* __restrict__ ea) {
    int idx = blockIdx.x * blockDim.x + threadIdx.x;
    if (idx >= EE * 4) return;
    int e = idx >> 2;
    int q = idx & 3;
    int j = q * 8;
    int s = ei[e];
    int d = ei[EE + e];
    float4 ea0 = ((const float4*)(ea + e * EF))[0];
    float4 ea1 = ((const float4*)(ea + e * EF))[1];
    const __half* y = dY2h + (size_t)s * (EF * L2) + j;
    float4 m0 = *(const float4*)(dZ2 + s * L2 + j);
    float4 m1 = *(const float4*)(dZ2 + s * L2 + j + 4);
#define E2STEP(F, A) { \
    uint4 r = *(const uint4*)(y + (F) * L2); \
    float2 f0 = __half22float2(*reinterpret_cast<const __half2*>(&r.x)); \
    float2 f1 = __half22float2(*reinterpret_cast<const __half2*>(&r.y)); \
    float2 f2 = __half22float2(*reinterpret_cast<const __half2*>(&r.z)); \
    float2 f3 = __half22float2(*reinterpret_cast<const __half2*>(&r.w)); \
    m0.x += (A) * f0.x; m0.y += (A) * f0.y; m0.z += (A) * f1.x; m0.w += (A) * f1.y; \
    m1.x += (A) * f2.x; m1.y += (A) * f2.y; m1.z += (A) * f3.x; m1.w += (A) * f3.y; }
    E2STEP(0, ea0.x) E2STEP(1, ea0.y) E2STEP(2, ea0.z) E2STEP(3, ea0.w)
    E2STEP(4, ea1.x) E2STEP(5, ea1.y) E2STEP(6, ea1.z) E2STEP(7, ea1.w)
#undef E2STEP
    red_add_v4(&dAgg2[d * L2 + j], m0);
    red_add_v4(&dAgg2[d * L2 + j + 4], m1);
}

// ---------------- kernel: h2 relu + head GEMV + out self-term ---------------
__global__ void node3_kernel(const float* __restrict__ mu_b, const float* __restrict__ ls_b,
                             float* __restrict__ out) {
    int idx = blockIdx.x * blockDim.x + threadIdx.x;
    if (idx >= NN * 32) return;
    int n = idx >> 5;
    int c = idx & 31;
    const float* a = dAgg2 + n * L2;
    const float* w = dWgT + c * 32;
    float acc = 0.0f;
#pragma unroll
    for (int k = 0; k < 32; k++) acc += fmaxf(a[k], 0.0f) * w[k];
    dG[idx] = acc;
    float rs = dRs[n];
    float inv = rs * rs;  // 1/deg
    if (c < OUTC) out[n * OUTC + c] = acc * inv + mu_b[c];
    else          out[(size_t)NN * OUTC + n * OUTC + (c - OUTC)] = acc * inv + ls_b[c - OUTC];
}

// ---------------- kernel: GCN edge aggregation (8 cols/thread) --------------
__global__ void edge3_kernel(const int* __restrict__ ei, float* __restrict__ out) {
    int idx = blockIdx.x * blockDim.x + threadIdx.x;
    if (idx >= EE * 4) return;
    int e = idx >> 2;
    int q = idx & 3;
    int c = q * 8;   // groups [0,8),[8,16) mu ; [16,24),[24,32) ls
    int s = ei[e];
    int d = ei[EE + e];
    float norm = dRs[s] * dRs[d];
    float4 g0 = *(const float4*)(dG + s * 32 + c);
    float4 g1 = *(const float4*)(dG + s * 32 + c + 4);
    g0.x *= norm; g0.y *= norm; g0.z *= norm; g0.w *= norm;
    g1.x *= norm; g1.y *= norm; g1.z *= norm; g1.w *= norm;
    float* dst = (c < OUTC) ? &out[d * OUTC + c]
                            : &out[(size_t)NN * OUTC + d * OUTC + (c - OUTC)];
    red_add_v4(dst, g0);
    red_add_v4(dst + 4, g1);
}

// ---------------- launch ----------------------------------------------------
extern "C" void kernel_launch(void* const* d_in, const int* in_sizes, int n_in,
                              void* d_out, int out_size) {
    const float* x     = (const float*)d_in[0];
    const int*   ei    = (const int*)  d_in[1];
    const float* ea    = (const float*)d_in[2];
    const float* nn1_w = (const float*)d_in[3];
    const float* nn1_b = (const float*)d_in[4];
    const float* root1 = (const float*)d_in[5];
    const float* bias1 = (const float*)d_in[6];
    const float* nn2_w = (const float*)d_in[7];
    const float* nn2_b = (const float*)d_in[8];
    const float* root2 = (const float*)d_in[9];
    const float* bias2 = (const float*)d_in[10];
    const float* mu_w  = (const float*)d_in[11];
    const float* mu_b  = (const float*)d_in[12];
    const float* ls_w  = (const float*)d_in[13];
    const float* ls_b  = (const float*)d_in[14];
    float* out = (float*)d_out;

    int prep_threads = C1TOT * 64 + C2TOT * 48 + 32 * 32;
    prep_weights<<<(prep_threads + 255) / 256, 256>>>(nn1_w, nn1_b, root1,
                                                      nn2_w, nn2_b, root2, mu_w, ls_w);
    node1_kernel<<<NN / NPB, C1TOT>>>(x, bias1);
    edge1_kernel<<<(EE * 6 + 255) / 256, 256>>>(ei, ea);
    node2_kernel<<<NN / NPB2, C2TOT>>>(bias2);
    edge2_kernel<<<(EE * 4 + 255) / 256, 256>>>(ei, ea);
    node3_kernel<<<(NN * 32 + 255) / 256, 256>>>(mu_b, ls_b, out);
    edge3_kernel<<<(EE * 4 + 255) / 256, 256>>>(ei, out);
}

// round 14
// speedup vs baseline: 2.2632x; 2.2632x over previous
#include <cuda_runtime.h>
#include <cuda_bf16.h>
#include <cuda_fp16.h>

// Problem constants (shapes fixed by the dataset)
#define NN   8192
#define EE   65536
#define INC  64
#define OUTC 16
#define EF   8
#define L1   48
#define L2   32

#define C1TOT 480   // Y1 (EF*L1=384) + Z1 (48) + R1 (48), K=64
#define C2TOT 320   // Y2 (EF*L2=256) + Z2 (32) + R2 (32), K=48

#define NPB 16  // nodes per block (register tile height)

// ---------------- scratch (device globals; no allocation allowed) ----------
__device__ __half dY1h[(size_t)NN * EF * L1];  // fp16 gather payload  6.3 MB
__device__ __half dZ1h[NN * L1];               // fp16 gather payload
__device__ float  dAgg1[NN * L1];
__device__ __half dY2h[(size_t)NN * EF * L2];  // fp16 gather payload  4.2 MB
__device__ __half dZ2h[NN * L2];               // fp16 gather payload
__device__ float  dAgg2[NN * L2];
__device__ float  dDeg[NN];
__device__ float  dRs[NN];                     // rsqrt(deg)
__device__ float  dG[NN * 2 * OUTC];           // [n][c], c<16 mu, c>=16 ls
__device__ float  dW1km[64 * C1TOT];           // k-major: [k][c]
__device__ float  dW2km[48 * C2TOT];           // k-major: [k][c]
__device__ float  dWgKM[32 * 32];              // k-major: [k][c]

__device__ __forceinline__ void red_add_v4(float* addr, float4 v) {
    asm volatile("red.global.add.v4.f32 [%0], {%1, %2, %3, %4};"
                 :: "l"(addr), "f"(v.x), "f"(v.y), "f"(v.z), "f"(v.w) : "memory");
}
__device__ __forceinline__ void fma2(unsigned long long& acc, unsigned long long a,
                                     unsigned long long b) {
    asm("fma.rn.f32x2 %0, %1, %2, %0;" : "+l"(acc) : "l"(a), "l"(b));
}
__device__ __forceinline__ unsigned long long pack2(float w) {
    unsigned long long r;
    asm("mov.b64 %0, {%1, %1};" : "=l"(r) : "f"(w));
    return r;
}
__device__ __forceinline__ void unpack2(unsigned long long v, float& lo, float& hi) {
    asm("mov.b64 {%0, %1}, %2;" : "=f"(lo), "=f"(hi) : "l"(v));
}

// ---------------- kernel 0: weight pre-transpose (k-major) ------------------
__global__ void prep_weights(const float* __restrict__ nn1_w, const float* __restrict__ nn1_b,
                             const float* __restrict__ root1,
                             const float* __restrict__ nn2_w, const float* __restrict__ nn2_b,
                             const float* __restrict__ root2,
                             const float* __restrict__ mu_w,  const float* __restrict__ ls_w) {
    int idx = blockIdx.x * blockDim.x + threadIdx.x;
    if (idx < C1TOT * 64) {
        int k = idx / C1TOT, c = idx - k * C1TOT;
        float v;
        if (c < EF * L1)            { int f = c / L1, j = c % L1; v = nn1_w[f * (INC * L1) + k * L1 + j]; }
        else if (c < EF * L1 + L1)  { int j = c - EF * L1;        v = nn1_b[k * L1 + j]; }
        else                        { int j = c - EF * L1 - L1;   v = root1[k * L1 + j]; }
        dW1km[idx] = v;
    }
    int i2 = idx - C1TOT * 64;
    if (i2 >= 0 && i2 < C2TOT * 48) {
        int k = i2 / C2TOT, c = i2 - k * C2TOT;
        float v;
        if (c < EF * L2)            { int f = c / L2, j = c % L2; v = nn2_w[f * (L1 * L2) + k * L2 + j]; }
        else if (c < EF * L2 + L2)  { int j = c - EF * L2;        v = nn2_b[k * L2 + j]; }
        else                        { int j = c - EF * L2 - L2;   v = root2[k * L2 + j]; }
        dW2km[i2] = v;
    }
    int i3 = i2 - C2TOT * 48;
    if (i3 >= 0 && i3 < 32 * 32) {
        int k = i3 >> 5, c = i3 & 31;   // k-major output: [k][c]
        dWgKM[i3] = (c < OUTC) ? mu_w[k * OUTC + c] : ls_w[k * OUTC + (c - OUTC)];
    }
}

// ---------------- kernel: node transform layer 1 (f32x2 packed) -------------
// xs transposed: [k][n]. One output column per thread.
__global__ __launch_bounds__(C1TOT) void node1_kernel(const float* __restrict__ x,
                                                      const float* __restrict__ bias1) {
    __shared__ float xs[64 * NPB];
    int n0 = blockIdx.x * NPB;
    int c = threadIdx.x;
    if (c < 256) {                       // 16 nodes x 16 k-groups of 4
        int n = c & 15, k0 = (c >> 4) * 4;
        float4 v = *(const float4*)(x + (size_t)(n0 + n) * 64 + k0);
        xs[(k0 + 0) * NPB + n] = v.x;
        xs[(k0 + 1) * NPB + n] = v.y;
        xs[(k0 + 2) * NPB + n] = v.z;
        xs[(k0 + 3) * NPB + n] = v.w;
    }
    if (c < NPB) dDeg[n0 + c] = 1.0f;
    __syncthreads();

    unsigned long long acc2[NPB / 2];
#pragma unroll
    for (int p = 0; p < NPB / 2; p++) acc2[p] = 0ull;
    const float* wp = dW1km + c;
#pragma unroll 4
    for (int k = 0; k < 64; k++) {
        unsigned long long w2 = pack2(wp[k * C1TOT]);
        const ulonglong2* xp = (const ulonglong2*)(xs + k * NPB);
#pragma unroll
        for (int i = 0; i < NPB / 4; i++) {
            ulonglong2 xv = xp[i];
            fma2(acc2[2 * i + 0], xv.x, w2);
            fma2(acc2[2 * i + 1], xv.y, w2);
        }
    }
    float acc[NPB];
#pragma unroll
    for (int p = 0; p < NPB / 2; p++) unpack2(acc2[p], acc[2 * p], acc[2 * p + 1]);

    if (c < EF * L1) {
#pragma unroll
        for (int n = 0; n < NPB; n++)
            dY1h[(size_t)(n0 + n) * (EF * L1) + c] = __float2half(acc[n]);
    } else if (c < EF * L1 + L1) {
        int j = c - EF * L1;
#pragma unroll
        for (int n = 0; n < NPB; n++) dZ1h[(n0 + n) * L1 + j] = __float2half(acc[n]);
    } else {
        int j = c - EF * L1 - L1;
        float b = bias1[j];
#pragma unroll
        for (int n = 0; n < NPB; n++) dAgg1[(n0 + n) * L1 + j] = acc[n] + b;
    }
}

// ---------------- kernel: edge scatter layer 1 (fp16 gather, vec4 red) ------
__global__ void edge1_kernel(const int* __restrict__ ei, const float* __restrict__ ea) {
    int idx = blockIdx.x * blockDim.x + threadIdx.x;
    if (idx >= EE * 12) return;
    int e = idx / 12;
    int q = idx - e * 12;
    int j = q * 4;
    int s = ei[e];
    int d = ei[EE + e];
    float4 ea0 = ((const float4*)(ea + e * EF))[0];
    float4 ea1 = ((const float4*)(ea + e * EF))[1];
    const __half* y = dY1h + (size_t)s * (EF * L1) + j;
    uint2 zr = *(const uint2*)(dZ1h + s * L1 + j);
    float2 z0 = __half22float2(*reinterpret_cast<const __half2*>(&zr.x));
    float2 z1 = __half22float2(*reinterpret_cast<const __half2*>(&zr.y));
    float4 m = make_float4(z0.x, z0.y, z1.x, z1.y);
#define E1STEP(F, A) { \
    uint2 r = *(const uint2*)(y + (F) * L1); \
    float2 f0 = __half22float2(*reinterpret_cast<const __half2*>(&r.x)); \
    float2 f1 = __half22float2(*reinterpret_cast<const __half2*>(&r.y)); \
    m.x += (A) * f0.x; m.y += (A) * f0.y; m.z += (A) * f1.x; m.w += (A) * f1.y; }
    E1STEP(0, ea0.x) E1STEP(1, ea0.y) E1STEP(2, ea0.z) E1STEP(3, ea0.w)
    E1STEP(4, ea1.x) E1STEP(5, ea1.y) E1STEP(6, ea1.z) E1STEP(7, ea1.w)
#undef E1STEP
    if (q == 0) atomicAdd(&dDeg[d], 1.0f);
    red_add_v4(&dAgg1[d * L1 + j], m);
}

// ---------------- kernel: node transform layer 2 (scalar) -------------------
__global__ __launch_bounds__(C2TOT) void node2_kernel(const float* __restrict__ bias2) {
    __shared__ float hs[NPB * 48];
    int n0 = blockIdx.x * NPB;
    int c = threadIdx.x;
    if (c < NPB * 48 / 4) {
        float4 v = ((const float4*)(dAgg1 + n0 * L1))[c];
        v.x = fmaxf(v.x, 0.f); v.y = fmaxf(v.y, 0.f);
        v.z = fmaxf(v.z, 0.f); v.w = fmaxf(v.w, 0.f);
        ((float4*)hs)[c] = v;
    }
    if (c < NPB) dRs[n0 + c] = rsqrtf(dDeg[n0 + c]);  // deg final after edge1
    __syncthreads();

    float acc[NPB];
#pragma unroll
    for (int n = 0; n < NPB; n++) acc[n] = 0.0f;
    const float* wp = dW2km + c;
#pragma unroll 8
    for (int k4 = 0; k4 < 12; k4++) {
        float w0 = wp[(4 * k4 + 0) * C2TOT];
        float w1 = wp[(4 * k4 + 1) * C2TOT];
        float w2 = wp[(4 * k4 + 2) * C2TOT];
        float w3 = wp[(4 * k4 + 3) * C2TOT];
#pragma unroll
        for (int n = 0; n < NPB; n++) {
            float4 xv = ((const float4*)(hs + n * 48))[k4];  // broadcast LDS
            acc[n] += xv.x * w0 + xv.y * w1 + xv.z * w2 + xv.w * w3;
        }
    }
    if (c < EF * L2) {
#pragma unroll
        for (int n = 0; n < NPB; n++)
            dY2h[(size_t)(n0 + n) * (EF * L2) + c] = __float2half(acc[n]);
    } else if (c < EF * L2 + L2) {
        int j = c - EF * L2;
#pragma unroll
        for (int n = 0; n < NPB; n++) dZ2h[(n0 + n) * L2 + j] = __float2half(acc[n]);
    } else {
        int j = c - EF * L2 - L2;
        float b = bias2[j];
#pragma unroll
        for (int n = 0; n < NPB; n++) dAgg2[(n0 + n) * L2 + j] = acc[n] + b;
    }
}

// ---------------- kernel: edge scatter layer 2 (fp16 gather, vec4 red) ------
__global__ void edge2_kernel(const int* __restrict__ ei, const float* __restrict__ ea) {
    int idx = blockIdx.x * blockDim.x + threadIdx.x;
    if (idx >= EE * 8) return;
    int e = idx >> 3;
    int q = idx & 7;
    int j = q * 4;
    int s = ei[e];
    int d = ei[EE + e];
    float4 ea0 = ((const float4*)(ea + e * EF))[0];
    float4 ea1 = ((const float4*)(ea + e * EF))[1];
    const __half* y = dY2h + (size_t)s * (EF * L2) + j;
    uint2 zr = *(const uint2*)(dZ2h + s * L2 + j);
    float2 z0 = __half22float2(*reinterpret_cast<const __half2*>(&zr.x));
    float2 z1 = __half22float2(*reinterpret_cast<const __half2*>(&zr.y));
    float4 m = make_float4(z0.x, z0.y, z1.x, z1.y);
#define E2STEP(F, A) { \
    uint2 r = *(const uint2*)(y + (F) * L2); \
    float2 f0 = __half22float2(*reinterpret_cast<const __half2*>(&r.x)); \
    float2 f1 = __half22float2(*reinterpret_cast<const __half2*>(&r.y)); \
    m.x += (A) * f0.x; m.y += (A) * f0.y; m.z += (A) * f1.x; m.w += (A) * f1.y; }
    E2STEP(0, ea0.x) E2STEP(1, ea0.y) E2STEP(2, ea0.z) E2STEP(3, ea0.w)
    E2STEP(4, ea1.x) E2STEP(5, ea1.y) E2STEP(6, ea1.z) E2STEP(7, ea1.w)
#undef E2STEP
    red_add_v4(&dAgg2[d * L2 + j], m);
}

// ---------------- kernel: h2 relu + head GEMV + out self-term ---------------
__global__ void node3_kernel(const float* __restrict__ mu_b, const float* __restrict__ ls_b,
                             float* __restrict__ out) {
    int idx = blockIdx.x * blockDim.x + threadIdx.x;
    if (idx >= NN * 32) return;
    int n = idx >> 5;
    int c = idx & 31;
    const float* a = dAgg2 + n * L2;
    float acc = 0.0f;
#pragma unroll
    for (int k = 0; k < 32; k++) acc += fmaxf(a[k], 0.0f) * dWgKM[k * 32 + c];
    dG[idx] = acc;
    float rs = dRs[n];
    float inv = rs * rs;  // 1/deg
    if (c < OUTC) out[n * OUTC + c] = acc * inv + mu_b[c];
    else          out[(size_t)NN * OUTC + n * OUTC + (c - OUTC)] = acc * inv + ls_b[c - OUTC];
}

// ---------------- kernel: GCN edge aggregation (vec4 red) -------------------
__global__ void edge3_kernel(const int* __restrict__ ei, float* __restrict__ out) {
    int idx = blockIdx.x * blockDim.x + threadIdx.x;
    if (idx >= EE * 8) return;
    int e = idx >> 3;
    int q = idx & 7;
    int c = q * 4;
    int s = ei[e];
    int d = ei[EE + e];
    float norm = dRs[s] * dRs[d];
    float4 g = *(const float4*)(dG + s * 32 + c);
    g.x *= norm; g.y *= norm; g.z *= norm; g.w *= norm;
    float* dst = (c < OUTC) ? &out[d * OUTC + c]
                            : &out[(size_t)NN * OUTC + d * OUTC + (c - OUTC)];
    red_add_v4(dst, g);
}

// ---------------- launch ----------------------------------------------------
extern "C" void kernel_launch(void* const* d_in, const int* in_sizes, int n_in,
                              void* d_out, int out_size) {
    const float* x     = (const float*)d_in[0];
    const int*   ei    = (const int*)  d_in[1];
    const float* ea    = (const float*)d_in[2];
    const float* nn1_w = (const float*)d_in[3];
    const float* nn1_b = (const float*)d_in[4];
    const float* root1 = (const float*)d_in[5];
    const float* bias1 = (const float*)d_in[6];
    const float* nn2_w = (const float*)d_in[7];
    const float* nn2_b = (const float*)d_in[8];
    const float* root2 = (const float*)d_in[9];
    const float* bias2 = (const float*)d_in[10];
    const float* mu_w  = (const float*)d_in[11];
    const float* mu_b  = (const float*)d_in[12];
    const float* ls_w  = (const float*)d_in[13];
    const float* ls_b  = (const float*)d_in[14];
    float* out = (float*)d_out;

    int prep_threads = C1TOT * 64 + C2TOT * 48 + 32 * 32;
    prep_weights<<<(prep_threads + 255) / 256, 256>>>(nn1_w, nn1_b, root1,
                                                      nn2_w, nn2_b, root2, mu_w, ls_w);
    node1_kernel<<<NN / NPB, C1TOT>>>(x, bias1);
    edge1_kernel<<<(EE * 12 + 255) / 256, 256>>>(ei, ea);
    node2_kernel<<<NN / NPB, C2TOT>>>(bias2);
    edge2_kernel<<<(EE * 8 + 255) / 256, 256>>>(ei, ea);
    node3_kernel<<<(NN * 32 + 255) / 256, 256>>>(mu_b, ls_b, out);
    edge3_kernel<<<(EE * 8 + 255) / 256, 256>>>(ei, out);
}